// round 1
// baseline (speedup 1.0000x reference)
#include <cuda_runtime.h>
#include <math.h>

#define THREADS 256
#define M_TILE  32
#define KC      32
#define NEXP    256
#define H       4096
#define TOPK    8

// Padded smem strides (reduce bank conflicts, keep 16B alignment for float4)
#define AS_STRIDE 36
#define BS_STRIDE 260

__global__ __launch_bounds__(THREADS) void moe_gate_kernel(
    const float* __restrict__ x,   // [T, 4096]
    const float* __restrict__ w,   // [256, 4096]
    float*       __restrict__ out, // [T*8 idx][T*8 weight]
    int T)
{
    __shared__ float As[KC][AS_STRIDE];   // As[k][m] = x[row_base+m][k0+k]
    __shared__ float Bs[KC][BS_STRIDE];   // Bs[k][e] = w[e][k0+k]

    const int tid  = threadIdx.x;
    const int warp = tid >> 5;
    const int lane = tid & 31;
    const int row_base = blockIdx.x * M_TILE;

    // accumulators: rows warp*4 .. warp*4+3, experts lane*8 .. lane*8+7
    float acc[4][8];
    #pragma unroll
    for (int i = 0; i < 4; i++)
        #pragma unroll
        for (int j = 0; j < 8; j++)
            acc[i][j] = 0.0f;

    // x-load mapping: thread loads x[row_base + xm][k0 + xk .. +3] (float4)
    const int xm = tid >> 3;          // 0..31
    const int xk = (tid & 7) * 4;     // 0,4,..,28
    // w-load mapping: thread loads w[we + r*32][k0 + wk .. +3], r = 0..7
    const int we = tid >> 3;          // 0..31
    const int wk = (tid & 7) * 4;     // 0,4,..,28

    const float* xrow = x + (size_t)(row_base + xm) * H + xk;

    for (int k0 = 0; k0 < H; k0 += KC) {
        // stage x tile (transposed)
        float4 xa = *(const float4*)(xrow + k0);
        As[xk + 0][xm] = xa.x;
        As[xk + 1][xm] = xa.y;
        As[xk + 2][xm] = xa.z;
        As[xk + 3][xm] = xa.w;
        // stage w tile (transposed)
        #pragma unroll
        for (int r = 0; r < 8; r++) {
            int e = we + r * 32;
            float4 wv = *(const float4*)(w + (size_t)e * H + k0 + wk);
            Bs[wk + 0][e] = wv.x;
            Bs[wk + 1][e] = wv.y;
            Bs[wk + 2][e] = wv.z;
            Bs[wk + 3][e] = wv.w;
        }
        __syncthreads();

        #pragma unroll
        for (int k = 0; k < KC; k++) {
            float4 a  = *(const float4*)&As[k][warp * 4];       // broadcast within warp
            float4 b0 = *(const float4*)&Bs[k][lane * 8];
            float4 b1 = *(const float4*)&Bs[k][lane * 8 + 4];
            float av[4] = {a.x, a.y, a.z, a.w};
            float bv[8] = {b0.x, b0.y, b0.z, b0.w, b1.x, b1.y, b1.z, b1.w};
            #pragma unroll
            for (int i = 0; i < 4; i++)
                #pragma unroll
                for (int j = 0; j < 8; j++)
                    acc[i][j] = fmaf(av[i], bv[j], acc[i][j]);
        }
        __syncthreads();
    }

    // ---- gating: each warp owns rows warp*4..+3; its 32 lanes hold all 256 logits ----
    #pragma unroll
    for (int i = 0; i < 4; i++) {
        const int row = row_base + warp * 4 + i;
        if (row >= T) continue;

        float v[8];
        #pragma unroll
        for (int j = 0; j < 8; j++) v[j] = acc[i][j];

        unsigned msk = 0u;
        float bestv[TOPK];
        int   besti[TOPK];

        #pragma unroll
        for (int t = 0; t < TOPK; t++) {
            // local argmax over unmasked (ascending j keeps lowest index on tie)
            float bv = -INFINITY;
            int   bi = 0x7fffffff;
            #pragma unroll
            for (int j = 0; j < 8; j++) {
                bool ok = ((msk >> j) & 1u) == 0u;
                if (ok && v[j] > bv) { bv = v[j]; bi = lane * 8 + j; }
            }
            // warp argmax: larger value wins; ties -> smaller index (jax top_k stable order)
            #pragma unroll
            for (int off = 16; off > 0; off >>= 1) {
                float ov = __shfl_xor_sync(0xffffffffu, bv, off);
                int   oi = __shfl_xor_sync(0xffffffffu, bi, off);
                if (ov > bv || (ov == bv && oi < bi)) { bv = ov; bi = oi; }
            }
            bestv[t] = bv;
            besti[t] = bi;
            if ((bi >> 3) == lane) msk |= 1u << (bi & 7);
        }

        const float mx = bestv[0];   // global max logit

        // full softmax denominator over all 256 experts
        float s = 0.0f;
        #pragma unroll
        for (int j = 0; j < 8; j++) s += expf(v[j] - mx);
        #pragma unroll
        for (int off = 16; off > 0; off >>= 1)
            s += __shfl_xor_sync(0xffffffffu, s, off);
        const float invZ = 1.0f / s;

        // top-k probs, renormalize, scale (matches reference order of ops)
        float p[TOPK];
        float tsum = 0.0f;
        #pragma unroll
        for (int t = 0; t < TOPK; t++) {
            p[t] = expf(bestv[t] - mx) * invZ;
            tsum += p[t];
        }
        const float scale = 2.5f / (tsum + 1e-20f);

        if (lane == 0) {
            const size_t base = (size_t)row * TOPK;
            const size_t woff = (size_t)T * TOPK;
            #pragma unroll
            for (int t = 0; t < TOPK; t++) {
                out[base + t]        = (float)besti[t];
                out[woff + base + t] = p[t] * scale;
            }
        }
    }
}

extern "C" void kernel_launch(void* const* d_in, const int* in_sizes, int n_in,
                              void* d_out, int out_size) {
    const float* x = (const float*)d_in[0];   // hidden_states [4,4096,4096] -> [T, 4096]
    const float* w = (const float*)d_in[1];   // weight [256, 4096]
    float* out = (float*)d_out;

    int T = in_sizes[0] / H;                  // 16384
    int grid = (T + M_TILE - 1) / M_TILE;     // 512
    moe_gate_kernel<<<grid, THREADS>>>(x, w, out, T);
}

// round 2
// speedup vs baseline: 1.0010x; 1.0010x over previous
#include <cuda_runtime.h>
#include <math.h>

#define THREADS 256
#define M_TILE  32
#define KC      32
#define NEXP    256
#define H       4096
#define TOPK    8

// Padded smem strides (reduce bank conflicts, keep 16B alignment for float4)
#define AS_STRIDE 36
#define BS_STRIDE 260

__global__ __launch_bounds__(THREADS) void moe_gate_kernel(
    const float* __restrict__ x,   // [T, 4096]
    const float* __restrict__ w,   // [256, 4096]
    float*       __restrict__ out, // [T*8 idx][T*8 weight]
    int T)
{
    __shared__ float As[KC][AS_STRIDE];   // As[k][m] = x[row_base+m][k0+k]
    __shared__ float Bs[KC][BS_STRIDE];   // Bs[k][e] = w[e][k0+k]

    const int tid  = threadIdx.x;
    const int warp = tid >> 5;
    const int lane = tid & 31;
    const int row_base = blockIdx.x * M_TILE;

    // accumulators: rows warp*4 .. warp*4+3, experts lane*8 .. lane*8+7
    float acc[4][8];
    #pragma unroll
    for (int i = 0; i < 4; i++)
        #pragma unroll
        for (int j = 0; j < 8; j++)
            acc[i][j] = 0.0f;

    // x-load mapping: thread loads x[row_base + xm][k0 + xk .. +3] (float4)
    const int xm = tid >> 3;          // 0..31
    const int xk = (tid & 7) * 4;     // 0,4,..,28
    // w-load mapping: thread loads w[we + r*32][k0 + wk .. +3], r = 0..7
    const int we = tid >> 3;          // 0..31
    const int wk = (tid & 7) * 4;     // 0,4,..,28

    const float* xrow = x + (size_t)(row_base + xm) * H + xk;

    for (int k0 = 0; k0 < H; k0 += KC) {
        // stage x tile (transposed)
        float4 xa = *(const float4*)(xrow + k0);
        As[xk + 0][xm] = xa.x;
        As[xk + 1][xm] = xa.y;
        As[xk + 2][xm] = xa.z;
        As[xk + 3][xm] = xa.w;
        // stage w tile (transposed)
        #pragma unroll
        for (int r = 0; r < 8; r++) {
            int e = we + r * 32;
            float4 wv = *(const float4*)(w + (size_t)e * H + k0 + wk);
            Bs[wk + 0][e] = wv.x;
            Bs[wk + 1][e] = wv.y;
            Bs[wk + 2][e] = wv.z;
            Bs[wk + 3][e] = wv.w;
        }
        __syncthreads();

        #pragma unroll
        for (int k = 0; k < KC; k++) {
            float4 a  = *(const float4*)&As[k][warp * 4];       // broadcast within warp
            float4 b0 = *(const float4*)&Bs[k][lane * 8];
            float4 b1 = *(const float4*)&Bs[k][lane * 8 + 4];
            float av[4] = {a.x, a.y, a.z, a.w};
            float bv[8] = {b0.x, b0.y, b0.z, b0.w, b1.x, b1.y, b1.z, b1.w};
            #pragma unroll
            for (int i = 0; i < 4; i++)
                #pragma unroll
                for (int j = 0; j < 8; j++)
                    acc[i][j] = fmaf(av[i], bv[j], acc[i][j]);
        }
        __syncthreads();
    }

    // ---- gating: each warp owns rows warp*4..+3; its 32 lanes hold all 256 logits ----
    #pragma unroll
    for (int i = 0; i < 4; i++) {
        const int row = row_base + warp * 4 + i;
        if (row >= T) continue;

        float v[8];
        #pragma unroll
        for (int j = 0; j < 8; j++) v[j] = acc[i][j];

        unsigned msk = 0u;
        float bestv[TOPK];
        int   besti[TOPK];

        #pragma unroll
        for (int t = 0; t < TOPK; t++) {
            // local argmax over unmasked (ascending j keeps lowest index on tie)
            float bv = -INFINITY;
            int   bi = 0x7fffffff;
            #pragma unroll
            for (int j = 0; j < 8; j++) {
                bool ok = ((msk >> j) & 1u) == 0u;
                if (ok && v[j] > bv) { bv = v[j]; bi = lane * 8 + j; }
            }
            // warp argmax: larger value wins; ties -> smaller index (jax top_k stable order)
            #pragma unroll
            for (int off = 16; off > 0; off >>= 1) {
                float ov = __shfl_xor_sync(0xffffffffu, bv, off);
                int   oi = __shfl_xor_sync(0xffffffffu, bi, off);
                if (ov > bv || (ov == bv && oi < bi)) { bv = ov; bi = oi; }
            }
            bestv[t] = bv;
            besti[t] = bi;
            if ((bi >> 3) == lane) msk |= 1u << (bi & 7);
        }

        const float mx = bestv[0];   // global max logit

        // full softmax denominator over all 256 experts
        float s = 0.0f;
        #pragma unroll
        for (int j = 0; j < 8; j++) s += expf(v[j] - mx);
        #pragma unroll
        for (int off = 16; off > 0; off >>= 1)
            s += __shfl_xor_sync(0xffffffffu, s, off);
        const float invZ = 1.0f / s;

        // top-k probs, renormalize, scale (matches reference order of ops)
        float p[TOPK];
        float tsum = 0.0f;
        #pragma unroll
        for (int t = 0; t < TOPK; t++) {
            p[t] = expf(bestv[t] - mx) * invZ;
            tsum += p[t];
        }
        const float scale = 2.5f / (tsum + 1e-20f);

        if (lane == 0) {
            const size_t base = (size_t)row * TOPK;
            const size_t woff = (size_t)T * TOPK;
            #pragma unroll
            for (int t = 0; t < TOPK; t++) {
                out[base + t]        = (float)besti[t];
                out[woff + base + t] = p[t] * scale;
            }
        }
    }
}

extern "C" void kernel_launch(void* const* d_in, const int* in_sizes, int n_in,
                              void* d_out, int out_size) {
    const float* x = (const float*)d_in[0];   // hidden_states [4,4096,4096] -> [T, 4096]
    const float* w = (const float*)d_in[1];   // weight [256, 4096]
    float* out = (float*)d_out;

    int T = in_sizes[0] / H;                  // 16384
    int grid = (T + M_TILE - 1) / M_TILE;     // 512
    moe_gate_kernel<<<grid, THREADS>>>(x, w, out, T);
}

// round 6
// speedup vs baseline: 2.5811x; 2.5785x over previous
#include <cuda_runtime.h>
#include <cuda_bf16.h>
#include <stdint.h>
#include <math.h>

#define HDIM   4096
#define NEXP   256
#define KC     32
#define NCHUNK 128
#define MTILE  64
#define TOPK   8

#define A_SP    4096                 // one A split tile: 64 rows x 64B
#define B_SP    16384                // one B split tile: 256 rows x 64B
#define A_BYTES (3*A_SP)             // 12288
#define B_BYTES (3*B_SP)             // 49152
#define STAGE   (A_BYTES + B_BYTES)  // 61440
#define SM_BASE 1024
#define SMEM_BYTES (SM_BASE + 2*STAGE)  // 123904
#define LSTR 260

// Pre-split, pre-swizzled W: [chunk][3 splits][16KB]
__device__ __align__(128) uint8_t g_wt[(size_t)NCHUNK * B_BYTES];

__device__ __forceinline__ uint32_t smem_u32(const void* p) {
    uint32_t a;
    asm("{ .reg .u64 t; cvta.to.shared.u64 t, %1; cvt.u32.u64 %0, t; }" : "=r"(a) : "l"(p));
    return a;
}
__device__ __forceinline__ uint32_t swz64(uint32_t o) { return o ^ ((o >> 3) & 0x30); }

__device__ __forceinline__ uint32_t packbf(float hi, float lo) {
    uint32_t r;
    asm("cvt.rn.bf16x2.f32 %0, %1, %2;" : "=r"(r) : "f"(hi), "f"(lo));
    return r;  // low 16 = bf16(lo) (elem k), high 16 = bf16(hi) (elem k+1)
}
__device__ __forceinline__ void split3(float x0, float x1, uint32_t& h, uint32_t& m, uint32_t& l) {
    h = packbf(x1, x0);
    float h0 = __uint_as_float(h << 16), h1 = __uint_as_float(h & 0xffff0000u);
    float r0 = x0 - h0, r1 = x1 - h1;
    m = packbf(r1, r0);
    float m0 = __uint_as_float(m << 16), m1 = __uint_as_float(m & 0xffff0000u);
    l = packbf(r1 - m1, r0 - m0);
}

__device__ __forceinline__ void mbar_init(uint32_t a, uint32_t c) {
    asm volatile("mbarrier.init.shared.b64 [%0], %1;" :: "r"(a), "r"(c) : "memory");
}
__device__ __forceinline__ void mbar_expect_tx(uint32_t a, uint32_t b) {
    asm volatile("mbarrier.arrive.expect_tx.shared.b64 _, [%0], %1;" :: "r"(a), "r"(b) : "memory");
}
__device__ __forceinline__ void mbar_wait(uint32_t a, uint32_t ph) {
    uint32_t done;
    asm volatile("{\n\t.reg .pred p;\n\t"
                 "mbarrier.try_wait.parity.acquire.cta.shared::cta.b64 p, [%1], %2;\n\t"
                 "selp.b32 %0,1,0,p;\n\t}" : "=r"(done) : "r"(a), "r"(ph) : "memory");
    if (!done) {
        asm volatile("{\n\t.reg .pred P;\n"
                     "W0_%=:\n\t"
                     "mbarrier.try_wait.parity.acquire.cta.shared::cta.b64 P, [%0], %1, 0x989680;\n\t"
                     "@P bra W1_%=;\n\t"
                     "bra W0_%=;\n"
                     "W1_%=:\n\t}" :: "r"(a), "r"(ph) : "memory");
    }
}
__device__ __forceinline__ void bulk_cp(uint32_t dst, const void* src, uint32_t bytes, uint32_t mbar) {
    asm volatile("cp.async.bulk.shared::cluster.global.mbarrier::complete_tx::bytes "
                 "[%0], [%1], %2, [%3];"
                 :: "r"(dst), "l"(src), "r"(bytes), "r"(mbar) : "memory");
}

#define LDSM4(r, addr)                                                           \
    asm volatile("ldmatrix.sync.aligned.m8n8.x4.shared.b16 {%0,%1,%2,%3}, [%4];" \
        : "=r"((r)[0]), "=r"((r)[1]), "=r"((r)[2]), "=r"((r)[3]) : "r"(addr))

// window-accumulate: c += a*b
#define MMA_ACC(c, a, b0v, b1v)                                                  \
    asm volatile("mma.sync.aligned.m16n8k16.row.col.f32.bf16.bf16.f32 "          \
        "{%0,%1,%2,%3}, {%4,%5,%6,%7}, {%8,%9}, {%0,%1,%2,%3};"                  \
        : "+f"((c)[0]), "+f"((c)[1]), "+f"((c)[2]), "+f"((c)[3])                 \
        : "r"((a)[0]), "r"((a)[1]), "r"((a)[2]), "r"((a)[3]), "r"(b0v), "r"(b1v))

// window-start: c = a*b + 0
#define MMA_NEW(c, a, b0v, b1v)                                                  \
    asm volatile("mma.sync.aligned.m16n8k16.row.col.f32.bf16.bf16.f32 "          \
        "{%0,%1,%2,%3}, {%4,%5,%6,%7}, {%8,%9}, {%10,%10,%10,%10};"              \
        : "=f"((c)[0]), "=f"((c)[1]), "=f"((c)[2]), "=f"((c)[3])                 \
        : "r"((a)[0]), "r"((a)[1]), "r"((a)[2]), "r"((a)[3]), "r"(b0v), "r"(b1v),\
          "f"(0.0f))

// ---------------- W pre-split kernel: grid=128 chunks, 256 thr = expert rows ----
__global__ void __launch_bounds__(256) wprep_kernel(const float* __restrict__ w) {
    const int c = blockIdx.x;
    const int e = threadIdx.x;
    const float4* src = (const float4*)(w + (size_t)e * HDIM + c * KC);
    float xv[32];
    #pragma unroll
    for (int i = 0; i < 8; i++) {
        float4 f = src[i];
        xv[i*4+0]=f.x; xv[i*4+1]=f.y; xv[i*4+2]=f.z; xv[i*4+3]=f.w;
    }
    uint32_t hh[16], mm_[16], ll[16];
    #pragma unroll
    for (int j = 0; j < 16; j++) split3(xv[2*j], xv[2*j+1], hh[j], mm_[j], ll[j]);
    uint8_t* base = g_wt + (size_t)c * B_BYTES;
    #pragma unroll
    for (int b = 0; b < 4; b++) {
        uint32_t so = swz64((uint32_t)e * 64 + b * 16);
        *(uint4*)(base + 0*B_SP + so) = make_uint4(hh[4*b],hh[4*b+1],hh[4*b+2],hh[4*b+3]);
        *(uint4*)(base + 1*B_SP + so) = make_uint4(mm_[4*b],mm_[4*b+1],mm_[4*b+2],mm_[4*b+3]);
        *(uint4*)(base + 2*B_SP + so) = make_uint4(ll[4*b],ll[4*b+1],ll[4*b+2],ll[4*b+3]);
    }
}

// ---------------- main kernel: grid = T/64, 256 threads (8 warps 2Mx4N) --------
__global__ void __launch_bounds__(256, 1)
moe_gate_mma(const float* __restrict__ x, float* __restrict__ out, int T) {
    extern __shared__ __align__(1024) uint8_t smem[];
    const uint32_t sbase = smem_u32(smem);
    const int tid  = threadIdx.x;
    const int wid  = tid >> 5;
    const int lane = tid & 31;
    const int row_base = blockIdx.x * MTILE;

    if (tid == 0) { mbar_init(sbase + 16, 1); mbar_init(sbase + 24, 1); }

    // A staging: thread -> row = tid/4 (0..63), 8 k-elems at (tid%4)*8
    const int arow = tid >> 2;
    const int aq   = tid & 3;
    const float* xrow = x + (size_t)(row_base + arow) * HDIM + aq * 8;
    const uint32_t a_sts = swz64((uint32_t)arow * 64 + aq * 16);

    // warp tile: 32M x 64N
    const int wm = wid & 1, wn = wid >> 1;
    const int m0 = wm * 32, n0 = wn * 64;

    // precomputed swizzled ldmatrix offsets (relative to split tile base)
    uint32_t aoff[2][2], boff[2][4];
    {
        uint32_t a_row = (uint32_t)(m0 + (lane & 15));
        uint32_t a_kh  = (uint32_t)(lane >> 4) * 16;
        uint32_t b_n   = (uint32_t)(n0 + (lane & 7) + ((lane >> 4) & 1) * 8);
        uint32_t b_kh  = (uint32_t)((lane >> 3) & 1) * 16;
        #pragma unroll
        for (int ks = 0; ks < 2; ks++) {
            #pragma unroll
            for (int mi = 0; mi < 2; mi++)
                aoff[ks][mi] = swz64((a_row + mi*16) * 64 + ks*32 + a_kh);
            #pragma unroll
            for (int nb = 0; nb < 4; nb++)
                boff[ks][nb] = swz64((b_n + nb*16) * 64 + ks*32 + b_kh);
        }
    }

    float master[2][8][4];   // fp32-RN running sum
    float winc[2][8][4];     // correction-product window (chained, small |C|)
    #pragma unroll
    for (int mi = 0; mi < 2; mi++)
        #pragma unroll
        for (int j = 0; j < 8; j++)
            #pragma unroll
            for (int q = 0; q < 4; q++)
                master[mi][j][q] = 0.0f;

    __syncthreads();   // mbarriers visible

    // prologue: stage chunk 0, prefetch x chunk 1
    if (tid == 0) {
        mbar_expect_tx(sbase + 16, B_BYTES);
        bulk_cp(sbase + SM_BASE + A_BYTES, g_wt, B_BYTES, sbase + 16);
    }
    float4 xa = *(const float4*)(xrow);
    float4 xb = *(const float4*)(xrow + 4);
    {
        uint32_t h[4], m[4], l[4];
        split3(xa.x, xa.y, h[0], m[0], l[0]);
        split3(xa.z, xa.w, h[1], m[1], l[1]);
        split3(xb.x, xb.y, h[2], m[2], l[2]);
        split3(xb.z, xb.w, h[3], m[3], l[3]);
        *(uint4*)(smem + SM_BASE + 0*A_SP + a_sts) = make_uint4(h[0],h[1],h[2],h[3]);
        *(uint4*)(smem + SM_BASE + 1*A_SP + a_sts) = make_uint4(m[0],m[1],m[2],m[3]);
        *(uint4*)(smem + SM_BASE + 2*A_SP + a_sts) = make_uint4(l[0],l[1],l[2],l[3]);
    }
    xa = *(const float4*)(xrow + KC);
    xb = *(const float4*)(xrow + KC + 4);
    __syncthreads();

    for (int i = 0; i < NCHUNK; i++) {
        const int s = i & 1;
        const uint32_t stoff = SM_BASE + (uint32_t)s * STAGE;

        mbar_wait(sbase + 16 + 8*s, (i >> 1) & 1);

        if (i < NCHUNK - 1) {
            const uint32_t nstoff = SM_BASE + (uint32_t)(s ^ 1) * STAGE;
            if (tid == 0) {
                mbar_expect_tx(sbase + 16 + 8*(s^1), B_BYTES);
                bulk_cp(sbase + nstoff + A_BYTES, g_wt + (size_t)(i+1) * B_BYTES,
                        B_BYTES, sbase + 16 + 8*(s^1));
            }
            uint32_t h[4], m[4], l[4];
            split3(xa.x, xa.y, h[0], m[0], l[0]);
            split3(xa.z, xa.w, h[1], m[1], l[1]);
            split3(xb.x, xb.y, h[2], m[2], l[2]);
            split3(xb.z, xb.w, h[3], m[3], l[3]);
            *(uint4*)(smem + nstoff + 0*A_SP + a_sts) = make_uint4(h[0],h[1],h[2],h[3]);
            *(uint4*)(smem + nstoff + 1*A_SP + a_sts) = make_uint4(m[0],m[1],m[2],m[3]);
            *(uint4*)(smem + nstoff + 2*A_SP + a_sts) = make_uint4(l[0],l[1],l[2],l[3]);
            if (i < NCHUNK - 2) {
                xa = *(const float4*)(xrow + (size_t)(i+2) * KC);
                xb = *(const float4*)(xrow + (size_t)(i+2) * KC + 4);
            }
        }

        // ---- compute chunk i ----
        const uint32_t Ab = sbase + stoff;
        const uint32_t Bb = sbase + stoff + A_BYTES;
        const int nA[3] = {3, 2, 1};   // bh:{ah,am,al}  bm:{ah,am}  bl:{ah}
        bool corr_started = false;
        #pragma unroll
        for (int bs = 0; bs < 3; bs++) {
            #pragma unroll
            for (int ks = 0; ks < 2; ks++) {
                uint32_t Bf[4][4];
                #pragma unroll
                for (int nb = 0; nb < 4; nb++)
                    LDSM4(Bf[nb], Bb + bs*B_SP + boff[ks][nb]);
                #pragma unroll
                for (int as = 0; as < 3; as++) {
                    if (as < nA[bs]) {
                        uint32_t Af[2][4];
                        #pragma unroll
                        for (int mi = 0; mi < 2; mi++)
                            LDSM4(Af[mi], Ab + as*A_SP + aoff[ks][mi]);
                        if (bs == 0 && as == 0) {
                            // hh product: C=0 each step, immediate fp32-RN drain
                            float wh[2][8][4];
                            #pragma unroll
                            for (int mi = 0; mi < 2; mi++)
                                #pragma unroll
                                for (int nb = 0; nb < 4; nb++) {
                                    MMA_NEW(wh[mi][nb*2+0], Af[mi], Bf[nb][0], Bf[nb][1]);
                                    MMA_NEW(wh[mi][nb*2+1], Af[mi], Bf[nb][2], Bf[nb][3]);
                                }
                            #pragma unroll
                            for (int mi = 0; mi < 2; mi++)
                                #pragma unroll
                                for (int j = 0; j < 8; j++)
                                    #pragma unroll
                                    for (int q = 0; q < 4; q++)
                                        master[mi][j][q] += wh[mi][j][q];
                        } else if (!corr_started) {
                            corr_started = true;
                            #pragma unroll
                            for (int mi = 0; mi < 2; mi++)
                                #pragma unroll
                                for (int nb = 0; nb < 4; nb++) {
                                    MMA_NEW(winc[mi][nb*2+0], Af[mi], Bf[nb][0], Bf[nb][1]);
                                    MMA_NEW(winc[mi][nb*2+1], Af[mi], Bf[nb][2], Bf[nb][3]);
                                }
                        } else {
                            #pragma unroll
                            for (int mi = 0; mi < 2; mi++)
                                #pragma unroll
                                for (int nb = 0; nb < 4; nb++) {
                                    MMA_ACC(winc[mi][nb*2+0], Af[mi], Bf[nb][0], Bf[nb][1]);
                                    MMA_ACC(winc[mi][nb*2+1], Af[mi], Bf[nb][2], Bf[nb][3]);
                                }
                        }
                    }
                }
            }
        }
        // drain correction window (|C| during its chaining was ~2^-9 of hh)
        #pragma unroll
        for (int mi = 0; mi < 2; mi++)
            #pragma unroll
            for (int j = 0; j < 8; j++)
                #pragma unroll
                for (int q = 0; q < 4; q++)
                    master[mi][j][q] += winc[mi][j][q];

        __syncthreads();
    }

    // ---- epilogue: dump logits to smem, per-thread top-8 ----
    float* lg = (float*)(smem + SM_BASE);
    #pragma unroll
    for (int mi = 0; mi < 2; mi++)
        #pragma unroll
        for (int j = 0; j < 8; j++) {
            int r = m0 + mi*16 + (lane >> 2);
            int c = n0 + j*8 + 2*(lane & 3);
            *(float2*)&lg[(size_t)r * LSTR + c]       = make_float2(master[mi][j][0], master[mi][j][1]);
            *(float2*)&lg[(size_t)(r + 8) * LSTR + c] = make_float2(master[mi][j][2], master[mi][j][3]);
        }
    __syncthreads();

    if (tid < MTILE) {
        const int row = row_base + tid;
        float tv[TOPK]; int ti[TOPK];
        #pragma unroll
        for (int t = 0; t < TOPK; t++) { tv[t] = -INFINITY; ti[t] = 0x7fffffff; }
        const float* lr = &lg[(size_t)tid * LSTR];
        for (int g = 0; g < 64; g++) {
            float4 v4 = *(const float4*)(lr + g * 4);
            float vs[4] = {v4.x, v4.y, v4.z, v4.w};
            #pragma unroll
            for (int q = 0; q < 4; q++) {
                float v = vs[q];
                if (v > tv[TOPK-1]) {
                    tv[TOPK-1] = v; ti[TOPK-1] = g*4 + q;
                    #pragma unroll
                    for (int t = TOPK-1; t > 0; t--) {
                        if (tv[t] > tv[t-1]) {
                            float fv = tv[t]; tv[t] = tv[t-1]; tv[t-1] = fv;
                            int   fi = ti[t]; ti[t] = ti[t-1]; ti[t-1] = fi;
                        }
                    }
                }
            }
        }
        // Z cancels under top-k renorm: w_t = 2.5 * exp(v_t - mx) / sum
        float e[TOPK], ssum = 0.0f;
        #pragma unroll
        for (int t = 0; t < TOPK; t++) { e[t] = expf(tv[t] - tv[0]); ssum += e[t]; }
        const float scale = 2.5f / ssum;
        const size_t base = (size_t)row * TOPK;
        const size_t wofs = (size_t)T * TOPK;
        #pragma unroll
        for (int t = 0; t < TOPK; t++) {
            out[base + t]        = (float)ti[t];
            out[wofs + base + t] = e[t] * scale;
        }
    }
}

extern "C" void kernel_launch(void* const* d_in, const int* in_sizes, int n_in,
                              void* d_out, int out_size) {
    const float* x = (const float*)d_in[0];
    const float* w = (const float*)d_in[1];
    float* out = (float*)d_out;
    int T = in_sizes[0] / HDIM;   // 16384

    cudaFuncSetAttribute(moe_gate_mma, cudaFuncAttributeMaxDynamicSharedMemorySize, SMEM_BYTES);

    wprep_kernel<<<NCHUNK, 256>>>(w);
    moe_gate_mma<<<T / MTILE, 256, SMEM_BYTES>>>(x, out, T);
}

// round 7
// speedup vs baseline: 4.8532x; 1.8803x over previous
#include <cuda_runtime.h>
#include <cuda_fp16.h>
#include <stdint.h>
#include <math.h>

#define HDIM   4096
#define NEXP   256
#define KC     64
#define NCHUNK 64
#define MTILE  64
#define TOPK   8

#define A_SP    8192                 // one A split tile: 64 rows x 128B
#define B_SP    32768                // one B split tile: 256 rows x 128B
#define A_BYTES (2*A_SP)             // 16384
#define B_BYTES (2*B_SP)             // 65536
#define STAGE   (A_BYTES + B_BYTES)  // 81920
#define SM_BASE 1024
#define SMEM_BYTES (SM_BASE + 2*STAGE)  // 164864
#define LSTR 260

// Pre-split, pre-swizzled W (fp16 h + scaled-m): [chunk64][2 splits][32KB]
__device__ __align__(128) uint8_t g_wt[(size_t)NCHUNK * B_BYTES];

__device__ __forceinline__ uint32_t smem_u32(const void* p) {
    uint32_t a;
    asm("{ .reg .u64 t; cvta.to.shared.u64 t, %1; cvt.u32.u64 %0, t; }" : "=r"(a) : "l"(p));
    return a;
}
// SW128: row*128 + col  ->  col bits [6:4] ^= row bits [2:0]
__device__ __forceinline__ uint32_t swz128(uint32_t o) { return o ^ ((o >> 3) & 0x70); }

__device__ __forceinline__ uint32_t packh(float lo, float hi) {
    __half2 h = __floats2half2_rn(lo, hi);   // .x = lo (low 16) = elem k
    return *(uint32_t*)&h;
}
// x = h + m*2^-12, both fp16-normal range; residual <= ~2^-24 |x|
__device__ __forceinline__ void split2(float x0, float x1, uint32_t& h, uint32_t& m) {
    h = packh(x0, x1);
    __half2 hh = *(__half2*)&h;
    float h0 = __low2float(hh), h1 = __high2float(hh);
    m = packh((x0 - h0) * 4096.0f, (x1 - h1) * 4096.0f);
}

__device__ __forceinline__ void mbar_init(uint32_t a, uint32_t c) {
    asm volatile("mbarrier.init.shared.b64 [%0], %1;" :: "r"(a), "r"(c) : "memory");
}
__device__ __forceinline__ void mbar_expect_tx(uint32_t a, uint32_t b) {
    asm volatile("mbarrier.arrive.expect_tx.shared.b64 _, [%0], %1;" :: "r"(a), "r"(b) : "memory");
}
__device__ __forceinline__ void mbar_wait(uint32_t a, uint32_t ph) {
    uint32_t done;
    asm volatile("{\n\t.reg .pred p;\n\t"
                 "mbarrier.try_wait.parity.acquire.cta.shared::cta.b64 p, [%1], %2;\n\t"
                 "selp.b32 %0,1,0,p;\n\t}" : "=r"(done) : "r"(a), "r"(ph) : "memory");
    if (!done) {
        asm volatile("{\n\t.reg .pred P;\n"
                     "W0_%=:\n\t"
                     "mbarrier.try_wait.parity.acquire.cta.shared::cta.b64 P, [%0], %1, 0x989680;\n\t"
                     "@P bra W1_%=;\n\t"
                     "bra W0_%=;\n"
                     "W1_%=:\n\t}" :: "r"(a), "r"(ph) : "memory");
    }
}
__device__ __forceinline__ void bulk_cp(uint32_t dst, const void* src, uint32_t bytes, uint32_t mbar) {
    asm volatile("cp.async.bulk.shared::cluster.global.mbarrier::complete_tx::bytes "
                 "[%0], [%1], %2, [%3];"
                 :: "r"(dst), "l"(src), "r"(bytes), "r"(mbar) : "memory");
}

#define LDSM4(r, addr)                                                           \
    asm volatile("ldmatrix.sync.aligned.m8n8.x4.shared.b16 {%0,%1,%2,%3}, [%4];" \
        : "=r"((r)[0]), "=r"((r)[1]), "=r"((r)[2]), "=r"((r)[3]) : "r"(addr))

// chained accumulate: c += a*b
#define MMA_ACC(c, a, b0v, b1v)                                                  \
    asm volatile("mma.sync.aligned.m16n8k16.row.col.f32.f16.f16.f32 "            \
        "{%0,%1,%2,%3}, {%4,%5,%6,%7}, {%8,%9}, {%0,%1,%2,%3};"                  \
        : "+f"((c)[0]), "+f"((c)[1]), "+f"((c)[2]), "+f"((c)[3])                 \
        : "r"((a)[0]), "r"((a)[1]), "r"((a)[2]), "r"((a)[3]), "r"(b0v), "r"(b1v))

// fresh window: c = a*b + 0
#define MMA_NEW(c, a, b0v, b1v)                                                  \
    asm volatile("mma.sync.aligned.m16n8k16.row.col.f32.f16.f16.f32 "            \
        "{%0,%1,%2,%3}, {%4,%5,%6,%7}, {%8,%9}, {%10,%10,%10,%10};"              \
        : "=f"((c)[0]), "=f"((c)[1]), "=f"((c)[2]), "=f"((c)[3])                 \
        : "r"((a)[0]), "r"((a)[1]), "r"((a)[2]), "r"((a)[3]), "r"(b0v), "r"(b1v),\
          "f"(0.0f))

// ---------------- W pre-split kernel: grid=128 k32-chunks, 256 thr = experts ---
__global__ void __launch_bounds__(256) wprep_kernel(const float* __restrict__ w) {
    const int c32 = blockIdx.x;            // 0..127 (32-wide k chunks)
    const int e   = threadIdx.x;
    const int c64 = c32 >> 1;
    const int kh  = (c32 & 1) * 64;        // byte offset within 128B row
    const float4* src = (const float4*)(w + (size_t)e * HDIM + c32 * 32);
    float xv[32];
    #pragma unroll
    for (int i = 0; i < 8; i++) {
        float4 f = src[i];
        xv[i*4+0]=f.x; xv[i*4+1]=f.y; xv[i*4+2]=f.z; xv[i*4+3]=f.w;
    }
    uint32_t hh[16], mm_[16];
    #pragma unroll
    for (int j = 0; j < 16; j++) split2(xv[2*j], xv[2*j+1], hh[j], mm_[j]);
    uint8_t* base = g_wt + (size_t)c64 * B_BYTES;
    #pragma unroll
    for (int b = 0; b < 4; b++) {
        uint32_t so = swz128((uint32_t)e * 128 + kh + b * 16);
        *(uint4*)(base + 0*B_SP + so) = make_uint4(hh[4*b],hh[4*b+1],hh[4*b+2],hh[4*b+3]);
        *(uint4*)(base + 1*B_SP + so) = make_uint4(mm_[4*b],mm_[4*b+1],mm_[4*b+2],mm_[4*b+3]);
    }
}

// ---------------- main kernel: grid = T/64, 256 threads (8 warps 2Mx4N) --------
__global__ void __launch_bounds__(256, 1)
moe_gate_mma(const float* __restrict__ x, float* __restrict__ out, int T) {
    extern __shared__ __align__(1024) uint8_t smem[];
    const uint32_t sbase = smem_u32(smem);
    const int tid  = threadIdx.x;
    const int wid  = tid >> 5;
    const int lane = tid & 31;
    const int row_base = blockIdx.x * MTILE;

    if (tid == 0) { mbar_init(sbase + 16, 1); mbar_init(sbase + 24, 1); }

    // A staging: thread -> row = tid/4 (0..63), 16 k-elems at (tid%4)*16
    const int arow = tid >> 2;
    const int aq   = tid & 3;
    const float* xrow = x + (size_t)(row_base + arow) * HDIM + aq * 16;
    const uint32_t a_sts0 = swz128((uint32_t)arow * 128 + aq * 32);
    const uint32_t a_sts1 = swz128((uint32_t)arow * 128 + aq * 32 + 16);

    // warp tile: 32M x 64N  (8 warps = 2M x 4N)
    const int wm = wid & 1, wn = wid >> 1;
    const int m0 = wm * 32, n0 = wn * 64;

    // swizzled ldmatrix offsets: ks in 0..3 (k16 steps within KC=64)
    uint32_t aoff[4][2], boff[4][4];
    {
        uint32_t a_row = (uint32_t)(m0 + (lane & 15));
        uint32_t a_kh  = (uint32_t)(lane >> 4) * 16;
        uint32_t b_n   = (uint32_t)(n0 + (lane & 7) + ((lane >> 4) & 1) * 8);
        uint32_t b_kh  = (uint32_t)((lane >> 3) & 1) * 16;
        #pragma unroll
        for (int ks = 0; ks < 4; ks++) {
            #pragma unroll
            for (int mi = 0; mi < 2; mi++)
                aoff[ks][mi] = swz128((a_row + mi*16) * 128 + ks*32 + a_kh);
            #pragma unroll
            for (int nb = 0; nb < 4; nb++)
                boff[ks][nb] = swz128((b_n + nb*16) * 128 + ks*32 + b_kh);
        }
    }

    float master[2][8][4];   // fp32-RN sum of hh windows
    float winc[2][8][4];     // hm+mh window, chained ALL chunks, scaled 2^12
    #pragma unroll
    for (int mi = 0; mi < 2; mi++)
        #pragma unroll
        for (int j = 0; j < 8; j++)
            #pragma unroll
            for (int q = 0; q < 4; q++)
                { master[mi][j][q] = 0.0f; winc[mi][j][q] = 0.0f; }

    __syncthreads();   // mbarriers visible

    // prologue: stage chunk 0 (A split + TMA B), prefetch x chunk 1
    if (tid == 0) {
        mbar_expect_tx(sbase + 16, B_BYTES);
        bulk_cp(sbase + SM_BASE + A_BYTES, g_wt, B_BYTES, sbase + 16);
    }
    {
        float4 f0 = *(const float4*)(xrow);
        float4 f1 = *(const float4*)(xrow + 4);
        float4 f2 = *(const float4*)(xrow + 8);
        float4 f3 = *(const float4*)(xrow + 12);
        uint32_t h[8], m[8];
        split2(f0.x, f0.y, h[0], m[0]); split2(f0.z, f0.w, h[1], m[1]);
        split2(f1.x, f1.y, h[2], m[2]); split2(f1.z, f1.w, h[3], m[3]);
        split2(f2.x, f2.y, h[4], m[4]); split2(f2.z, f2.w, h[5], m[5]);
        split2(f3.x, f3.y, h[6], m[6]); split2(f3.z, f3.w, h[7], m[7]);
        *(uint4*)(smem + SM_BASE + 0*A_SP + a_sts0) = make_uint4(h[0],h[1],h[2],h[3]);
        *(uint4*)(smem + SM_BASE + 0*A_SP + a_sts1) = make_uint4(h[4],h[5],h[6],h[7]);
        *(uint4*)(smem + SM_BASE + 1*A_SP + a_sts0) = make_uint4(m[0],m[1],m[2],m[3]);
        *(uint4*)(smem + SM_BASE + 1*A_SP + a_sts1) = make_uint4(m[4],m[5],m[6],m[7]);
    }
    float4 xr0 = *(const float4*)(xrow + KC);
    float4 xr1 = *(const float4*)(xrow + KC + 4);
    float4 xr2 = *(const float4*)(xrow + KC + 8);
    float4 xr3 = *(const float4*)(xrow + KC + 12);
    __syncthreads();

    for (int i = 0; i < NCHUNK; i++) {
        const int s = i & 1;
        const uint32_t stoff = SM_BASE + (uint32_t)s * STAGE;

        mbar_wait(sbase + 16 + 8*s, (i >> 1) & 1);

        if (i < NCHUNK - 1) {
            const uint32_t nstoff = SM_BASE + (uint32_t)(s ^ 1) * STAGE;
            if (tid == 0) {
                mbar_expect_tx(sbase + 16 + 8*(s^1), B_BYTES);
                bulk_cp(sbase + nstoff + A_BYTES, g_wt + (size_t)(i+1) * B_BYTES,
                        B_BYTES, sbase + 16 + 8*(s^1));
            }
            uint32_t h[8], m[8];
            split2(xr0.x, xr0.y, h[0], m[0]); split2(xr0.z, xr0.w, h[1], m[1]);
            split2(xr1.x, xr1.y, h[2], m[2]); split2(xr1.z, xr1.w, h[3], m[3]);
            split2(xr2.x, xr2.y, h[4], m[4]); split2(xr2.z, xr2.w, h[5], m[5]);
            split2(xr3.x, xr3.y, h[6], m[6]); split2(xr3.z, xr3.w, h[7], m[7]);
            *(uint4*)(smem + nstoff + 0*A_SP + a_sts0) = make_uint4(h[0],h[1],h[2],h[3]);
            *(uint4*)(smem + nstoff + 0*A_SP + a_sts1) = make_uint4(h[4],h[5],h[6],h[7]);
            *(uint4*)(smem + nstoff + 1*A_SP + a_sts0) = make_uint4(m[0],m[1],m[2],m[3]);
            *(uint4*)(smem + nstoff + 1*A_SP + a_sts1) = make_uint4(m[4],m[5],m[6],m[7]);
            if (i < NCHUNK - 2) {
                xr0 = *(const float4*)(xrow + (size_t)(i+2) * KC);
                xr1 = *(const float4*)(xrow + (size_t)(i+2) * KC + 4);
                xr2 = *(const float4*)(xrow + (size_t)(i+2) * KC + 8);
                xr3 = *(const float4*)(xrow + (size_t)(i+2) * KC + 12);
            }
        }

        // ---- compute chunk i: 4 k16 steps, products hh (drained), mh+hm (chained) ----
        const uint32_t Ab = sbase + stoff;
        const uint32_t Bb = sbase + stoff + A_BYTES;
        #pragma unroll
        for (int ks = 0; ks < 4; ks++) {
            uint32_t Bf[4][4], Ah[2][4], Am[2][4];
            #pragma unroll
            for (int nb = 0; nb < 4; nb++)
                LDSM4(Bf[nb], Bb + boff[ks][nb]);            // B_h
            #pragma unroll
            for (int mi = 0; mi < 2; mi++)
                LDSM4(Ah[mi], Ab + aoff[ks][mi]);            // A_h
            #pragma unroll
            for (int mi = 0; mi < 2; mi++)
                LDSM4(Am[mi], Ab + A_SP + aoff[ks][mi]);     // A_m

            // hh: fresh C per MMA, drain in fp32 RN
            #pragma unroll
            for (int mi = 0; mi < 2; mi++) {
                float wh[8][4];
                #pragma unroll
                for (int nb = 0; nb < 4; nb++) {
                    MMA_NEW(wh[nb*2+0], Ah[mi], Bf[nb][0], Bf[nb][1]);
                    MMA_NEW(wh[nb*2+1], Ah[mi], Bf[nb][2], Bf[nb][3]);
                }
                #pragma unroll
                for (int j = 0; j < 8; j++)
                    #pragma unroll
                    for (int q = 0; q < 4; q++)
                        master[mi][j][q] += wh[j][q];
            }
            // mh: A_m x B_h into chained window
            #pragma unroll
            for (int mi = 0; mi < 2; mi++)
                #pragma unroll
                for (int nb = 0; nb < 4; nb++) {
                    MMA_ACC(winc[mi][nb*2+0], Am[mi], Bf[nb][0], Bf[nb][1]);
                    MMA_ACC(winc[mi][nb*2+1], Am[mi], Bf[nb][2], Bf[nb][3]);
                }
            // hm: load B_m (reuse Bf), A_h x B_m into chained window
            #pragma unroll
            for (int nb = 0; nb < 4; nb++)
                LDSM4(Bf[nb], Bb + B_SP + boff[ks][nb]);
            #pragma unroll
            for (int mi = 0; mi < 2; mi++)
                #pragma unroll
                for (int nb = 0; nb < 4; nb++) {
                    MMA_ACC(winc[mi][nb*2+0], Ah[mi], Bf[nb][0], Bf[nb][1]);
                    MMA_ACC(winc[mi][nb*2+1], Ah[mi], Bf[nb][2], Bf[nb][3]);
                }
        }
        __syncthreads();
    }

    // combine: logits = master + winc * 2^-12
    const float CS = 1.0f / 4096.0f;
    #pragma unroll
    for (int mi = 0; mi < 2; mi++)
        #pragma unroll
        for (int j = 0; j < 8; j++)
            #pragma unroll
            for (int q = 0; q < 4; q++)
                master[mi][j][q] = fmaf(winc[mi][j][q], CS, master[mi][j][q]);

    // ---- epilogue: dump logits to smem, per-thread top-8 ----
    float* lg = (float*)(smem + SM_BASE);
    #pragma unroll
    for (int mi = 0; mi < 2; mi++)
        #pragma unroll
        for (int j = 0; j < 8; j++) {
            int r = m0 + mi*16 + (lane >> 2);
            int c = n0 + j*8 + 2*(lane & 3);
            *(float2*)&lg[(size_t)r * LSTR + c]       = make_float2(master[mi][j][0], master[mi][j][1]);
            *(float2*)&lg[(size_t)(r + 8) * LSTR + c] = make_float2(master[mi][j][2], master[mi][j][3]);
        }
    __syncthreads();

    if (tid < MTILE) {
        const int row = row_base + tid;
        float tv[TOPK]; int ti[TOPK];
        #pragma unroll
        for (int t = 0; t < TOPK; t++) { tv[t] = -INFINITY; ti[t] = 0x7fffffff; }
        const float* lr = &lg[(size_t)tid * LSTR];
        for (int g = 0; g < 64; g++) {
            float4 v4 = *(const float4*)(lr + g * 4);
            float vs[4] = {v4.x, v4.y, v4.z, v4.w};
            #pragma unroll
            for (int q = 0; q < 4; q++) {
                float v = vs[q];
                if (v > tv[TOPK-1]) {
                    tv[TOPK-1] = v; ti[TOPK-1] = g*4 + q;
                    #pragma unroll
                    for (int t = TOPK-1; t > 0; t--) {
                        if (tv[t] > tv[t-1]) {
                            float fv = tv[t]; tv[t] = tv[t-1]; tv[t-1] = fv;
                            int   fi = ti[t]; ti[t] = ti[t-1]; ti[t-1] = fi;
                        }
                    }
                }
            }
        }
        // Z cancels under top-k renorm: w_t = 2.5 * exp(v_t - mx) / sum
        float e[TOPK], ssum = 0.0f;
        #pragma unroll
        for (int t = 0; t < TOPK; t++) { e[t] = expf(tv[t] - tv[0]); ssum += e[t]; }
        const float scale = 2.5f / ssum;
        const size_t base = (size_t)row * TOPK;
        const size_t wofs = (size_t)T * TOPK;
        #pragma unroll
        for (int t = 0; t < TOPK; t++) {
            out[base + t]        = (float)ti[t];
            out[wofs + base + t] = e[t] * scale;
        }
    }
}

extern "C" void kernel_launch(void* const* d_in, const int* in_sizes, int n_in,
                              void* d_out, int out_size) {
    const float* x = (const float*)d_in[0];
    const float* w = (const float*)d_in[1];
    float* out = (float*)d_out;
    int T = in_sizes[0] / HDIM;   // 16384

    cudaFuncSetAttribute(moe_gate_mma, cudaFuncAttributeMaxDynamicSharedMemorySize, SMEM_BYTES);

    wprep_kernel<<<128, 256>>>(w);
    moe_gate_mma<<<T / MTILE, 256, SMEM_BYTES>>>(x, out, T);
}